// round 1
// baseline (speedup 1.0000x reference)
#include <cuda_runtime.h>
#include <math.h>

// DoublePAN: two PANConv layers + log_softmax, computed sparsely from bitmask
// adjacency instead of the reference's dense 2048x2048 pan matrix.
//
// pan = w0*I + w1*A + w2*A^2 ; deg[i] = nnz of pan row i
// out = dinv .* (pan^T @ (dinv .* (x@W^T+b)))  with pan^T applied as
// w0*v + w1*Bv + w2*B(Bv),  B = A^T.
//
// All scratch is __device__ global (no allocation). All launches are plain
// kernel launches on the default stream (graph-capturable). atomicOr is
// idempotent -> deterministic; all float sums have a fixed per-thread order.

#define MAXN 2048
#define MAXNW (MAXN / 32)

__device__ unsigned g_Abits[MAXN * MAXNW];   // row i: targets t with A[i,t]=1
__device__ unsigned g_Bbits[MAXN * MAXNW];   // row i: sources s with A[s,i]=1 (B = A^T)
__device__ float    g_dinv[MAXN];
__device__ float    g_q [MAXN * 16];         // layer-1 dinv*h
__device__ float    g_t1[MAXN * 32];         // B @ (.)
__device__ float    g_t2[MAXN * 32];         // B @ B @ (.)
__device__ float    g_q2[MAXN * 32];         // layer-2 dinv*h2

__global__ void k_clear(int nwords) {
    int i = blockIdx.x * blockDim.x + threadIdx.x;
    if (i < nwords) { g_Abits[i] = 0u; g_Bbits[i] = 0u; }
}

__global__ void k_edges(const int* __restrict__ ei, int E, int nw) {
    int e = blockIdx.x * blockDim.x + threadIdx.x;
    if (e >= E) return;
    int s = ei[e];       // source (row of A)
    int t = ei[E + e];   // target (col of A)
    atomicOr(&g_Abits[s * nw + (t >> 5)], 1u << (t & 31));
    atomicOr(&g_Bbits[t * nw + (s >> 5)], 1u << (s & 31));
}

// deg[i] = popcount( {i} | Arow_i | OR_{j in Arow_i} Arow_j ) ; dinv = deg^-1/2
// One warp per row; each lane owns up to 2 of the nw mask words.
__global__ void k_deg(int N, int nw) {
    int gw   = (blockIdx.x * blockDim.x + threadIdx.x) >> 5;
    int lane = threadIdx.x & 31;
    if (gw >= N) return;
    const unsigned* arow = &g_Abits[gw * nw];
    unsigned acc0 = 0u, acc1 = 0u;
    if (lane < nw)      acc0 = arow[lane];
    if (lane + 32 < nw) acc1 = arow[lane + 32];
    int wi = gw >> 5;
    unsigned ib = 1u << (gw & 31);
    if (lane == wi)           acc0 |= ib;   // identity term (fw[0] != 0)
    else if (lane + 32 == wi) acc1 |= ib;
    for (int w = 0; w < nw; w++) {
        unsigned word = arow[w];             // broadcast load (all lanes same addr)
        while (word) {
            int b = __ffs(word) - 1; word &= word - 1;
            const unsigned* jr = &g_Abits[(w * 32 + b) * nw];
            if (lane < nw)      acc0 |= jr[lane];
            if (lane + 32 < nw) acc1 |= jr[lane + 32];
        }
    }
    int cnt = __popc(acc0) + __popc(acc1);
    cnt = __reduce_add_sync(0xffffffffu, cnt);
    if (lane == 0) g_dinv[gw] = rsqrtf((float)cnt);
}

// q = dinv .* (x @ W1^T + b1)   -- one thread per (row, out-channel)
__global__ void k_lin1(const float* __restrict__ x, const float* __restrict__ w,
                       const float* __restrict__ b, int N, int F, int H) {
    int gid = blockIdx.x * blockDim.x + threadIdx.x;
    if (gid >= N * H) return;
    int row = gid / H, c = gid % H;
    const float4* x4 = (const float4*)(x + (size_t)row * F);
    const float4* w4 = (const float4*)(w + (size_t)c * F);
    float acc = 0.f;
    int f4 = F >> 2;
    #pragma unroll 4
    for (int k = 0; k < f4; k++) {
        float4 a = x4[k], ww = w4[k];
        acc = fmaf(a.x, ww.x, acc);
        acc = fmaf(a.y, ww.y, acc);
        acc = fmaf(a.z, ww.z, acc);
        acc = fmaf(a.w, ww.w, acc);
    }
    g_q[row * H + c] = g_dinv[row] * (acc + b[c]);
}

// out[i][c] = sum_{j in Bbits row i} in[j][c]   (warp per row, lane = channel)
__global__ void k_spmm(const float* __restrict__ in, float* __restrict__ out,
                       int N, int W, int nw) {
    int gw   = (blockIdx.x * blockDim.x + threadIdx.x) >> 5;
    int lane = threadIdx.x & 31;
    if (gw >= N) return;
    const unsigned* brow = &g_Bbits[gw * nw];
    float acc = 0.f;
    for (int w = 0; w < nw; w++) {
        unsigned word = brow[w];
        while (word) {
            int b = __ffs(word) - 1; word &= word - 1;
            int j = w * 32 + b;
            if (lane < W) acc += in[j * W + lane];
        }
    }
    if (lane < W) out[gw * W + lane] = acc;
}

// layer-1 epilogue fused with layer-2 linear:
// h1 = relu(dinv * (f0*q + f1*t1 + f2*t2)) ; q2 = dinv * (h1 @ W2^T + b2)
__global__ void k_combine1(const float* __restrict__ fw, const float* __restrict__ w2,
                           const float* __restrict__ b2, int N, int H, int C) {
    __shared__ float sh[8][32];
    int wb = threadIdx.x >> 5, lane = threadIdx.x & 31;
    int row = blockIdx.x * 8 + wb;
    if (row >= N) return;
    float f0 = fw[0], f1 = fw[1], f2 = fw[2];
    float d = g_dinv[row];
    if (lane < H) {
        float r = f0 * g_q[row * H + lane] + f1 * g_t1[row * H + lane]
                + f2 * g_t2[row * H + lane];
        sh[wb][lane] = fmaxf(d * r, 0.f);
    }
    __syncwarp();
    if (lane < C) {
        float acc = b2[lane];
        for (int k = 0; k < H; k++) acc = fmaf(w2[lane * H + k], sh[wb][k], acc);
        g_q2[row * C + lane] = d * acc;
    }
}

// z = dinv*(f0*q2 + f1*t1 + f2*t2) ; out = log_softmax(z) per row
__global__ void k_final(const float* __restrict__ fw, float* __restrict__ out,
                        int N, int C) {
    int wb = threadIdx.x >> 5, lane = threadIdx.x & 31;
    int row = blockIdx.x * 8 + wb;
    if (row >= N) return;
    float f0 = fw[0], f1 = fw[1], f2 = fw[2];
    float d = g_dinv[row];
    float z = -INFINITY;
    if (lane < C)
        z = d * (f0 * g_q2[row * C + lane] + f1 * g_t1[row * C + lane]
               + f2 * g_t2[row * C + lane]);
    float m = z;
    #pragma unroll
    for (int o = 16; o; o >>= 1) m = fmaxf(m, __shfl_xor_sync(0xffffffffu, m, o));
    float e = (lane < C) ? __expf(z - m) : 0.f;
    float s = e;
    #pragma unroll
    for (int o = 16; o; o >>= 1) s += __shfl_xor_sync(0xffffffffu, s, o);
    if (lane < C) out[row * C + lane] = z - m - logf(s);
}

extern "C" void kernel_launch(void* const* d_in, const int* in_sizes, int n_in,
                              void* d_out, int out_size) {
    const float* x   = (const float*)d_in[0];
    const int*   ei  = (const int*)  d_in[1];
    const float* fw1 = (const float*)d_in[2];
    const float* w1  = (const float*)d_in[3];
    const float* b1  = (const float*)d_in[4];
    const float* fw2 = (const float*)d_in[5];
    const float* w2  = (const float*)d_in[6];
    const float* b2  = (const float*)d_in[7];
    float* out = (float*)d_out;

    int H = in_sizes[4];            // 16
    int F = in_sizes[3] / H;        // 512
    int N = in_sizes[0] / F;        // 2048
    int E = in_sizes[1] / 2;        // 32768
    int C = in_sizes[7];            // 32
    int nw = (N + 31) / 32;         // 64

    float *qp, *t1p, *t2p, *q2p;
    cudaGetSymbolAddress((void**)&qp,  g_q);
    cudaGetSymbolAddress((void**)&t1p, g_t1);
    cudaGetSymbolAddress((void**)&t2p, g_t2);
    cudaGetSymbolAddress((void**)&q2p, g_q2);

    int rowBlocks = (N + 7) / 8;    // 8 warps (rows) per 256-thread block

    k_clear<<<(N * nw + 255) / 256, 256>>>(N * nw);
    k_edges<<<(E + 255) / 256, 256>>>(ei, E, nw);
    k_deg<<<rowBlocks, 256>>>(N, nw);
    k_lin1<<<(N * H + 255) / 256, 256>>>(x, w1, b1, N, F, H);

    // layer 1: r = f0*q + f1*Bq + f2*BBq (width H)
    k_spmm<<<rowBlocks, 256>>>(qp,  t1p, N, H, nw);
    k_spmm<<<rowBlocks, 256>>>(t1p, t2p, N, H, nw);
    k_combine1<<<rowBlocks, 256>>>(fw1, w2, b2, N, H, C);

    // layer 2: width C
    k_spmm<<<rowBlocks, 256>>>(q2p, t1p, N, C, nw);
    k_spmm<<<rowBlocks, 256>>>(t1p, t2p, N, C, nw);
    k_final<<<rowBlocks, 256>>>(fw2, out, N, C);
}

// round 2
// speedup vs baseline: 1.2517x; 1.2517x over previous
#include <cuda_runtime.h>
#include <math.h>

// DoublePAN via bitmask adjacency. Round 2:
//  - k_lin1 rewritten as smem-tiled GEMM (coalesced x stream, W1^T resident
//    in smem, conflict-free [F][H] layout)
//  - deg fused into the same launch (independent block ranges)
//  - layer epilogues fused into the second SpMM of each layer (t2 in regs)
//  - clear via one cudaMemsetAsync node
// Math: out = d .* (f0*u + f1*B u + f2*B(B u)),  u = d .* (x@W^T + b),
//       B = A^T, d = deg(pan)^-1/2. dinv scaling moved into the first gather.

#define MAXN 2048
#define MAXNW (MAXN / 32)

__device__ unsigned g_bits[2 * MAXN * MAXNW]; // [0..N*nw): A rows, [N*nw..): B rows
__device__ float    g_dinv[MAXN];
__device__ float    g_q [MAXN * 16];          // h1 = x@W1^T + b1 (unscaled)
__device__ float    g_t1[MAXN * 32];          // B @ (.)  (width 16 then 32)
__device__ float    g_q2[MAXN * 32];          // dinv * h2

__global__ void k_edges(const int* __restrict__ ei, int E, int N, int nw) {
    int e = blockIdx.x * blockDim.x + threadIdx.x;
    if (e >= E) return;
    int s = ei[e];       // source (row of A)
    int t = ei[E + e];   // target (col of A)
    atomicOr(&g_bits[s * nw + (t >> 5)], 1u << (t & 31));
    atomicOr(&g_bits[(N + t) * nw + (s >> 5)], 1u << (s & 31));
}

// Fused: blocks [0, degBlocks) compute dinv (warp per row, bitset union+popc);
// blocks [degBlocks, ...) compute h1 = x@W1^T + b1 as a tiled GEMM.
__global__ void k_deglin(const float* __restrict__ x, const float* __restrict__ w,
                         const float* __restrict__ b, int N, int F, int nw,
                         int degBlocks) {
    __shared__ float wsT[512 * 16];   // W1^T: [f][c], bank-conflict-free
    __shared__ float xs[16][64];

    if (blockIdx.x < degBlocks) {
        // ---- degree path: warp per row ----
        int gw   = blockIdx.x * 8 + (threadIdx.x >> 5);
        int lane = threadIdx.x & 31;
        if (gw >= N) return;
        const unsigned* arow = &g_bits[gw * nw];
        unsigned acc0 = 0u, acc1 = 0u;
        if (lane < nw)      acc0 = arow[lane];
        if (lane + 32 < nw) acc1 = arow[lane + 32];
        int wi = gw >> 5;
        unsigned ib = 1u << (gw & 31);
        if (lane == wi)           acc0 |= ib;   // identity term
        else if (lane + 32 == wi) acc1 |= ib;
        for (int w2 = 0; w2 < nw; w2++) {
            unsigned word = arow[w2];
            while (word) {
                int bb = __ffs(word) - 1; word &= word - 1;
                const unsigned* jr = &g_bits[(w2 * 32 + bb) * nw];
                if (lane < nw)      acc0 |= jr[lane];
                if (lane + 32 < nw) acc1 |= jr[lane + 32];
            }
        }
        int cnt = __popc(acc0) + __popc(acc1);
        cnt = __reduce_add_sync(0xffffffffu, cnt);
        if (lane == 0) g_dinv[gw] = rsqrtf((float)cnt);
        return;
    }

    // ---- linear path: 16 rows per block ----
    int bid = blockIdx.x - degBlocks;
    int row0 = bid * 16;
    int tid = threadIdx.x;

    // stage W1 transposed: wsT[f*16 + c] = w[c*512 + f]; global reads coalesced
    for (int e = tid; e < 512 * 16; e += 256) {
        int c = e >> 9, f = e & 511;
        wsT[f * 16 + c] = w[e];
    }
    __syncthreads();

    int r = tid >> 4, c = tid & 15;
    float acc = 0.f;
    for (int kc = 0; kc < F; kc += 64) {
        // stage x tile [16 rows x 64 cols], coalesced
        for (int e = tid; e < 16 * 64; e += 256) {
            int rr = e >> 6, k = e & 63;
            xs[rr][k] = x[(size_t)(row0 + rr) * F + kc + k];
        }
        __syncthreads();
        #pragma unroll 8
        for (int k = 0; k < 64; k++)
            acc = fmaf(xs[r][k], wsT[(kc + k) * 16 + c], acc);
        __syncthreads();
    }
    g_q[(row0 + r) * 16 + c] = acc + b[c];
}

// t1[i][c] = sum_{j in B row i} dinv[j] * h[j][c]   (width 16; warp per row)
__global__ void k_spmm16(int N, int nw) {
    int gw   = blockIdx.x * 8 + (threadIdx.x >> 5);
    int lane = threadIdx.x & 31;
    if (gw >= N) return;
    const unsigned* brow = &g_bits[(N + gw) * nw];
    float acc = 0.f;
    for (int w = 0; w < nw; w++) {
        unsigned word = brow[w];
        while (word) {
            int b = __ffs(word) - 1; word &= word - 1;
            int j = w * 32 + b;
            if (lane < 16) acc = fmaf(g_dinv[j], g_q[j * 16 + lane], acc);
        }
    }
    if (lane < 16) g_t1[gw * 16 + lane] = acc;
}

// fused: t2 = B t1 (in regs); h1 = relu(d*(f0*d*h + f1*t1 + f2*t2));
// q2 = d * (h1 @ W2^T + b2)   (W2: [32][16])
__global__ void k_l1post(const float* __restrict__ fw, const float* __restrict__ w2,
                         const float* __restrict__ b2, int N, int nw) {
    int gw   = blockIdx.x * 8 + (threadIdx.x >> 5);
    int lane = threadIdx.x & 31;
    if (gw >= N) return;
    const unsigned* brow = &g_bits[(N + gw) * nw];
    float t2 = 0.f;
    for (int w = 0; w < nw; w++) {
        unsigned word = brow[w];
        while (word) {
            int b = __ffs(word) - 1; word &= word - 1;
            int j = w * 32 + b;
            if (lane < 16) t2 += g_t1[j * 16 + lane];
        }
    }
    float f0 = fw[0], f1 = fw[1], f2 = fw[2];
    float d = g_dinv[gw];
    float h1 = 0.f;
    if (lane < 16) {
        float r = f0 * d * g_q[gw * 16 + lane] + f1 * g_t1[gw * 16 + lane] + f2 * t2;
        h1 = fmaxf(d * r, 0.f);
    }
    // W2 GEMV via shuffles: lane = output channel c (0..31)
    float acc = b2[lane];
    #pragma unroll
    for (int k = 0; k < 16; k++) {
        float hk = __shfl_sync(0xffffffffu, h1, k);
        acc = fmaf(w2[lane * 16 + k], hk, acc);
    }
    g_q2[gw * 32 + lane] = d * acc;
}

// t1n[i][c] = sum_{j in B row i} q2[j][c]   (width 32; warp per row)
__global__ void k_spmm32(int N, int nw) {
    int gw   = blockIdx.x * 8 + (threadIdx.x >> 5);
    int lane = threadIdx.x & 31;
    if (gw >= N) return;
    const unsigned* brow = &g_bits[(N + gw) * nw];
    float acc = 0.f;
    for (int w = 0; w < nw; w++) {
        unsigned word = brow[w];
        while (word) {
            int b = __ffs(word) - 1; word &= word - 1;
            acc += g_t1[(w * 32 + b) * 32 + lane];
        }
    }
    g_q2[gw * 32 + lane] = acc;   // WRONG target? no -- see note below
}

// fused final: t2 = B t1n (in regs); z = d*(f0*q2 + f1*t1n + f2*t2);
// out = log_softmax(z)
__global__ void k_l2post(const float* __restrict__ fw, float* __restrict__ out,
                         int N, int nw) {
    int gw   = blockIdx.x * 8 + (threadIdx.x >> 5);
    int lane = threadIdx.x & 31;
    if (gw >= N) return;
    const unsigned* brow = &g_bits[(N + gw) * nw];
    float t2 = 0.f;
    for (int w = 0; w < nw; w++) {
        unsigned word = brow[w];
        while (word) {
            int b = __ffs(word) - 1; word &= word - 1;
            t2 += g_t1[(w * 32 + b) * 32 + lane];
        }
    }
    float f0 = fw[0], f1 = fw[1], f2 = fw[2];
    float d = g_dinv[gw];
    float z = d * (f0 * g_q2[gw * 32 + lane] + f1 * g_t1[gw * 32 + lane] + f2 * t2);
    float m = z;
    #pragma unroll
    for (int o = 16; o; o >>= 1) m = fmaxf(m, __shfl_xor_sync(0xffffffffu, m, o));
    float e = __expf(z - m);
    float s = e;
    #pragma unroll
    for (int o = 16; o; o >>= 1) s += __shfl_xor_sync(0xffffffffu, s, o);
    out[gw * 32 + lane] = z - m - logf(s);
}

// layer-2 first SpMM must write into a separate buffer from its input (q2).
// g_t1 (width 32) is the input to k_spmm32? No: layer-2 structure is
//   u2 = q2; t1n = B u2; t2 = B t1n.
// So k_spmm32 reads q2 and must write t1n. Fixing the buffers here:
__global__ void k_spmm32b(int N, int nw) {
    int gw   = blockIdx.x * 8 + (threadIdx.x >> 5);
    int lane = threadIdx.x & 31;
    if (gw >= N) return;
    const unsigned* brow = &g_bits[(N + gw) * nw];
    float acc = 0.f;
    for (int w = 0; w < nw; w++) {
        unsigned word = brow[w];
        while (word) {
            int b = __ffs(word) - 1; word &= word - 1;
            acc += g_q2[(w * 32 + b) * 32 + lane];
        }
    }
    g_t1[gw * 32 + lane] = acc;
}

extern "C" void kernel_launch(void* const* d_in, const int* in_sizes, int n_in,
                              void* d_out, int out_size) {
    const float* x   = (const float*)d_in[0];
    const int*   ei  = (const int*)  d_in[1];
    const float* fw1 = (const float*)d_in[2];
    const float* w1  = (const float*)d_in[3];
    const float* b1  = (const float*)d_in[4];
    const float* fw2 = (const float*)d_in[5];
    const float* w2  = (const float*)d_in[6];
    const float* b2  = (const float*)d_in[7];
    float* out = (float*)d_out;

    int H = in_sizes[4];            // 16
    int F = in_sizes[3] / H;        // 512
    int N = in_sizes[0] / F;        // 2048
    int E = in_sizes[1] / 2;        // 32768
    int nw = (N + 31) / 32;         // 64

    void* bitsPtr;
    cudaGetSymbolAddress(&bitsPtr, g_bits);

    int rowBlocks = (N + 7) / 8;    // 256
    int degBlocks = rowBlocks;
    int linBlocks = (N + 15) / 16;  // 128

    cudaMemsetAsync(bitsPtr, 0, (size_t)2 * N * nw * sizeof(unsigned), 0);
    k_edges<<<(E + 255) / 256, 256>>>(ei, E, N, nw);
    k_deglin<<<degBlocks + linBlocks, 256>>>(x, w1, b1, N, F, nw, degBlocks);

    // layer 1
    k_spmm16<<<rowBlocks, 256>>>(N, nw);                 // t1 = B (d.*h)
    k_l1post<<<rowBlocks, 256>>>(fw1, w2, b2, N, nw);    // -> q2 = d.*h2

    // layer 2
    k_spmm32b<<<rowBlocks, 256>>>(N, nw);                // t1 = B q2
    k_l2post<<<rowBlocks, 256>>>(fw2, out, N, nw);       // log_softmax out
}

// round 3
// speedup vs baseline: 2.3530x; 1.8798x over previous
#include <cuda_runtime.h>
#include <math.h>

// DoublePAN via bitmask adjacency + CSR neighbor lists. Round 3:
//  - B-bitmask compacted to per-row CSR lists once (k_prep), so every SpMM
//    gather is MLP~8 batched independent L2 loads instead of a 64-step
//    serial word-scan chain.
//  - deg union also driven by an A-neighbor list (4-way OR batches).
//  - epilogues stay fused; 7 graph nodes total.

#define MAXN 2048
#define MAXNW (MAXN / 32)
#define CAP 128

__device__ unsigned g_bits[2 * MAXN * MAXNW]; // [0..N*nw): A rows, then B rows
__device__ int      g_nbrB[MAXN * CAP];
__device__ int      g_degB[MAXN];
__device__ float    g_dinv[MAXN];
__device__ float    g_q [MAXN * 16];          // h1 = x@W1^T + b1 (unscaled)
__device__ float    g_t1[MAXN * 32];          // B @ (.)
__device__ float    g_q2[MAXN * 32];          // dinv * h2

__global__ void k_edges(const int* __restrict__ ei, int E, int N, int nw) {
    int e = blockIdx.x * blockDim.x + threadIdx.x;
    if (e >= E) return;
    int s = ei[e], t = ei[E + e];
    atomicOr(&g_bits[s * nw + (t >> 5)], 1u << (t & 31));
    atomicOr(&g_bits[(N + t) * nw + (s >> 5)], 1u << (s & 31));
}

__device__ __forceinline__ int warp_exscan(int v, int lane) {
    int s = v;
    #pragma unroll
    for (int o = 1; o < 32; o <<= 1) {
        int u = __shfl_up_sync(0xffffffffu, s, o);
        if (lane >= o) s += u;
    }
    return s - v; // exclusive
}

// Fused: blocks [0, degBlocks): compact A->smem list, B->global CSR,
// compute deg via batched OR-union, dinv. Blocks [degBlocks,..): tiled GEMM.
__global__ void k_prep(const float* __restrict__ x, const float* __restrict__ w,
                       const float* __restrict__ b, int N, int F, int nw,
                       int degBlocks) {
    __shared__ float wsT[512 * 16];
    __shared__ float xs[16][64];
    __shared__ int   sA[8][CAP];

    if (blockIdx.x < degBlocks) {
        int wb = threadIdx.x >> 5, lane = threadIdx.x & 31;
        int row = blockIdx.x * 8 + wb;
        if (row >= N) return;
        const unsigned* arow = &g_bits[row * nw];
        const unsigned* brow = &g_bits[(N + row) * nw];
        int base = lane * 64;

        // ---- compact A row into smem list ----
        unsigned a0 = (2 * lane     < nw) ? arow[2 * lane]     : 0u;
        unsigned a1 = (2 * lane + 1 < nw) ? arow[2 * lane + 1] : 0u;
        int tot = __popc(a0) + __popc(a1);
        int off = warp_exscan(tot, lane);
        int degA = __shfl_sync(0xffffffffu, off + tot, 31);
        int pos = off;
        unsigned wt = a0;
        while (wt) { int bb = __ffs(wt) - 1; wt &= wt - 1; if (pos < CAP) sA[wb][pos] = base + bb; pos++; }
        wt = a1;
        while (wt) { int bb = __ffs(wt) - 1; wt &= wt - 1; if (pos < CAP) sA[wb][pos] = base + 32 + bb; pos++; }
        if (degA > CAP) degA = CAP;

        // ---- compact B row into global CSR ----
        unsigned b0 = (2 * lane     < nw) ? brow[2 * lane]     : 0u;
        unsigned b1 = (2 * lane + 1 < nw) ? brow[2 * lane + 1] : 0u;
        int totB = __popc(b0) + __popc(b1);
        int offB = warp_exscan(totB, lane);
        int degB = __shfl_sync(0xffffffffu, offB + totB, 31);
        int posB = offB;
        wt = b0;
        while (wt) { int bb = __ffs(wt) - 1; wt &= wt - 1; if (posB < CAP) g_nbrB[row * CAP + posB] = base + bb; posB++; }
        wt = b1;
        while (wt) { int bb = __ffs(wt) - 1; wt &= wt - 1; if (posB < CAP) g_nbrB[row * CAP + posB] = base + 32 + bb; posB++; }
        if (lane == 0) g_degB[row] = degB < CAP ? degB : CAP;
        __syncwarp();

        // ---- deg union: {row} | Arow | OR_{j in Arow} Arow_j ----
        unsigned acc0 = (lane < nw)      ? arow[lane]      : 0u;
        unsigned acc1 = (lane + 32 < nw) ? arow[lane + 32] : 0u;
        int wi = row >> 5; unsigned ib = 1u << (row & 31);
        if (lane == wi)           acc0 |= ib;
        else if (lane + 32 == wi) acc1 |= ib;
        int k = 0;
        for (; k + 4 <= degA; k += 4) {
            const unsigned* r0 = &g_bits[sA[wb][k]     * nw];
            const unsigned* r1 = &g_bits[sA[wb][k + 1] * nw];
            const unsigned* r2 = &g_bits[sA[wb][k + 2] * nw];
            const unsigned* r3 = &g_bits[sA[wb][k + 3] * nw];
            if (lane < nw)      acc0 |= r0[lane]      | r1[lane]      | r2[lane]      | r3[lane];
            if (lane + 32 < nw) acc1 |= r0[lane + 32] | r1[lane + 32] | r2[lane + 32] | r3[lane + 32];
        }
        for (; k < degA; k++) {
            const unsigned* r = &g_bits[sA[wb][k] * nw];
            if (lane < nw)      acc0 |= r[lane];
            if (lane + 32 < nw) acc1 |= r[lane + 32];
        }
        int cnt = __popc(acc0) + __popc(acc1);
        cnt = __reduce_add_sync(0xffffffffu, cnt);
        if (lane == 0) g_dinv[row] = rsqrtf((float)cnt);
        return;
    }

    // ---- GEMM path: h1 = x @ W1^T + b1, 16 rows per block ----
    int bid = blockIdx.x - degBlocks;
    int row0 = bid * 16;
    int tid = threadIdx.x;
    for (int e = tid; e < 512 * 16; e += 256) {
        int c = e >> 9, f = e & 511;
        wsT[f * 16 + c] = w[e];
    }
    __syncthreads();
    int r = tid >> 4, c = tid & 15;
    float acc = 0.f;
    for (int kc = 0; kc < F; kc += 64) {
        for (int e = tid; e < 16 * 64; e += 256) {
            int rr = e >> 6, k = e & 63;
            xs[rr][k] = x[(size_t)(row0 + rr) * F + kc + k];
        }
        __syncthreads();
        #pragma unroll 8
        for (int k = 0; k < 64; k++)
            acc = fmaf(xs[r][k], wsT[(kc + k) * 16 + c], acc);
        __syncthreads();
    }
    g_q[(row0 + r) * 16 + c] = acc + b[c];
}

// load this row's CSR list into smem (warp-local)
__device__ __forceinline__ int load_idx(int row, int wb, int lane, int (*sidx)[CAP]) {
    int deg = g_degB[row];
    for (int k = lane; k < deg; k += 32) sidx[wb][k] = g_nbrB[row * CAP + k];
    __syncwarp();
    return deg;
}

// t1[i][c] = sum_{j in B row i} dinv[j] * h1[j][c]   (width 16)
__global__ void k_spmm16(int N) {
    __shared__ int sidx[8][CAP];
    int wb = threadIdx.x >> 5, lane = threadIdx.x & 31;
    int row = blockIdx.x * 8 + wb;
    if (row >= N) return;
    int deg = load_idx(row, wb, lane, sidx);
    float acc = 0.f;
    int k = 0;
    for (; k + 8 <= deg; k += 8) {
        int j0 = sidx[wb][k],   j1 = sidx[wb][k+1], j2 = sidx[wb][k+2], j3 = sidx[wb][k+3];
        int j4 = sidx[wb][k+4], j5 = sidx[wb][k+5], j6 = sidx[wb][k+6], j7 = sidx[wb][k+7];
        if (lane < 16) {
            float v0 = g_dinv[j0] * g_q[j0*16+lane], v1 = g_dinv[j1] * g_q[j1*16+lane];
            float v2 = g_dinv[j2] * g_q[j2*16+lane], v3 = g_dinv[j3] * g_q[j3*16+lane];
            float v4 = g_dinv[j4] * g_q[j4*16+lane], v5 = g_dinv[j5] * g_q[j5*16+lane];
            float v6 = g_dinv[j6] * g_q[j6*16+lane], v7 = g_dinv[j7] * g_q[j7*16+lane];
            acc = acc + v0 + v1 + v2 + v3 + v4 + v5 + v6 + v7;
        }
    }
    for (; k < deg; k++) {
        int j = sidx[wb][k];
        if (lane < 16) acc += g_dinv[j] * g_q[j*16+lane];
    }
    if (lane < 16) g_t1[row * 16 + lane] = acc;
}

// fused: t2 = B t1; h1 = relu(d*(f0*d*h + f1*t1 + f2*t2)); q2 = d*(h1@W2^T+b2)
__global__ void k_l1post(const float* __restrict__ fw, const float* __restrict__ w2,
                         const float* __restrict__ b2, int N) {
    __shared__ int sidx[8][CAP];
    int wb = threadIdx.x >> 5, lane = threadIdx.x & 31;
    int row = blockIdx.x * 8 + wb;
    if (row >= N) return;
    int deg = load_idx(row, wb, lane, sidx);
    float t2 = 0.f;
    int k = 0;
    for (; k + 8 <= deg; k += 8) {
        int j0 = sidx[wb][k],   j1 = sidx[wb][k+1], j2 = sidx[wb][k+2], j3 = sidx[wb][k+3];
        int j4 = sidx[wb][k+4], j5 = sidx[wb][k+5], j6 = sidx[wb][k+6], j7 = sidx[wb][k+7];
        if (lane < 16) {
            t2 = t2 + g_t1[j0*16+lane] + g_t1[j1*16+lane] + g_t1[j2*16+lane]
                    + g_t1[j3*16+lane] + g_t1[j4*16+lane] + g_t1[j5*16+lane]
                    + g_t1[j6*16+lane] + g_t1[j7*16+lane];
        }
    }
    for (; k < deg; k++) {
        int j = sidx[wb][k];
        if (lane < 16) t2 += g_t1[j*16+lane];
    }
    float f0 = fw[0], f1 = fw[1], f2 = fw[2];
    float d = g_dinv[row];
    float h1 = 0.f;
    if (lane < 16) {
        float r = f0 * d * g_q[row*16+lane] + f1 * g_t1[row*16+lane] + f2 * t2;
        h1 = fmaxf(d * r, 0.f);
    }
    float acc = b2[lane];
    #pragma unroll
    for (int k2 = 0; k2 < 16; k2++) {
        float hk = __shfl_sync(0xffffffffu, h1, k2);
        acc = fmaf(w2[lane * 16 + k2], hk, acc);
    }
    g_q2[row * 32 + lane] = d * acc;
}

// t1[i][c] = sum_{j in B row i} q2[j][c]   (width 32)
__global__ void k_spmm32(int N) {
    __shared__ int sidx[8][CAP];
    int wb = threadIdx.x >> 5, lane = threadIdx.x & 31;
    int row = blockIdx.x * 8 + wb;
    if (row >= N) return;
    int deg = load_idx(row, wb, lane, sidx);
    float acc = 0.f;
    int k = 0;
    for (; k + 8 <= deg; k += 8) {
        int j0 = sidx[wb][k],   j1 = sidx[wb][k+1], j2 = sidx[wb][k+2], j3 = sidx[wb][k+3];
        int j4 = sidx[wb][k+4], j5 = sidx[wb][k+5], j6 = sidx[wb][k+6], j7 = sidx[wb][k+7];
        acc = acc + g_q2[j0*32+lane] + g_q2[j1*32+lane] + g_q2[j2*32+lane]
                  + g_q2[j3*32+lane] + g_q2[j4*32+lane] + g_q2[j5*32+lane]
                  + g_q2[j6*32+lane] + g_q2[j7*32+lane];
    }
    for (; k < deg; k++) acc += g_q2[sidx[wb][k]*32+lane];
    g_t1[row * 32 + lane] = acc;
}

// fused final: t2 = B t1; z = d*(f0*q2 + f1*t1 + f2*t2); out = log_softmax(z)
__global__ void k_l2post(const float* __restrict__ fw, float* __restrict__ out,
                         int N) {
    __shared__ int sidx[8][CAP];
    int wb = threadIdx.x >> 5, lane = threadIdx.x & 31;
    int row = blockIdx.x * 8 + wb;
    if (row >= N) return;
    int deg = load_idx(row, wb, lane, sidx);
    float t2 = 0.f;
    int k = 0;
    for (; k + 8 <= deg; k += 8) {
        int j0 = sidx[wb][k],   j1 = sidx[wb][k+1], j2 = sidx[wb][k+2], j3 = sidx[wb][k+3];
        int j4 = sidx[wb][k+4], j5 = sidx[wb][k+5], j6 = sidx[wb][k+6], j7 = sidx[wb][k+7];
        t2 = t2 + g_t1[j0*32+lane] + g_t1[j1*32+lane] + g_t1[j2*32+lane]
                + g_t1[j3*32+lane] + g_t1[j4*32+lane] + g_t1[j5*32+lane]
                + g_t1[j6*32+lane] + g_t1[j7*32+lane];
    }
    for (; k < deg; k++) t2 += g_t1[sidx[wb][k]*32+lane];
    float f0 = fw[0], f1 = fw[1], f2 = fw[2];
    float d = g_dinv[row];
    float z = d * (f0 * g_q2[row*32+lane] + f1 * g_t1[row*32+lane] + f2 * t2);
    float m = z;
    #pragma unroll
    for (int o = 16; o; o >>= 1) m = fmaxf(m, __shfl_xor_sync(0xffffffffu, m, o));
    float e = __expf(z - m);
    float s = e;
    #pragma unroll
    for (int o = 16; o; o >>= 1) s += __shfl_xor_sync(0xffffffffu, s, o);
    out[row * 32 + lane] = z - m - logf(s);
}

extern "C" void kernel_launch(void* const* d_in, const int* in_sizes, int n_in,
                              void* d_out, int out_size) {
    const float* x   = (const float*)d_in[0];
    const int*   ei  = (const int*)  d_in[1];
    const float* fw1 = (const float*)d_in[2];
    const float* w1  = (const float*)d_in[3];
    const float* b1  = (const float*)d_in[4];
    const float* fw2 = (const float*)d_in[5];
    const float* w2  = (const float*)d_in[6];
    const float* b2  = (const float*)d_in[7];
    float* out = (float*)d_out;

    int H = in_sizes[4];            // 16
    int F = in_sizes[3] / H;        // 512
    int N = in_sizes[0] / F;        // 2048
    int E = in_sizes[1] / 2;        // 32768
    int nw = (N + 31) / 32;         // 64

    void* bitsPtr;
    cudaGetSymbolAddress(&bitsPtr, g_bits);

    int rowBlocks = (N + 7) / 8;    // 256
    int linBlocks = (N + 15) / 16;  // 128

    cudaMemsetAsync(bitsPtr, 0, (size_t)2 * N * nw * sizeof(unsigned), 0);
    k_edges<<<(E + 255) / 256, 256>>>(ei, E, N, nw);
    k_prep<<<rowBlocks + linBlocks, 256>>>(x, w1, b1, N, F, nw, rowBlocks);

    k_spmm16<<<rowBlocks, 256>>>(N);
    k_l1post<<<rowBlocks, 256>>>(fw1, w2, b2, N);

    k_spmm32<<<rowBlocks, 256>>>(N);
    k_l2post<<<rowBlocks, 256>>>(fw2, out, N);
}

// round 4
// speedup vs baseline: 2.3602x; 1.0031x over previous
#include <cuda_runtime.h>
#include <math.h>

// DoublePAN, single persistent kernel. One graph node; software grid barrier
// (monotonic ticket counters -> safe across graph replays, no reset needed).
// Per-block smem keeps CSR lists + deg + dinv resident across all phases.
//
// Phases (6 grid barriers):
//  0 clear bitmasks | 1 edges atomicOr | 2 lists/deg/dinv (all blocks)
//    + GEMM h1=x@W1^T+b1 (first N/16 blocks, concurrent)
//  3 spmm16 t1=B(d.*h) | 4 l1post (t2=B t1, relu, W2 GEMV) ->q2=d.*h2
//  5 spmm32 t1=B q2    | final l2post (t2=B t1, log_softmax) -> out

#define MAXN 2048
#define MAXNW (MAXN / 32)
#define CAP 128
#define NTHR 256

__device__ unsigned g_bits[2 * MAXN * MAXNW]; // A rows then B rows
__device__ unsigned g_barctr[8];              // monotonic, never reset
__device__ float    g_dinv[MAXN];
__device__ float    g_q [MAXN * 16];          // h1 (unscaled)
__device__ float    g_t1[MAXN * 32];
__device__ float    g_q2[MAXN * 32];

__device__ __forceinline__ void gbar(int idx) {
    __threadfence();
    __syncthreads();
    if (threadIdx.x == 0) {
        unsigned nb = gridDim.x;
        unsigned t = atomicAdd(&g_barctr[idx], 1u);
        unsigned target = t - (t % nb) + nb;
        while ((int)(*(volatile unsigned*)&g_barctr[idx] - target) < 0)
            __nanosleep(32);
        __threadfence();
    }
    __syncthreads();
}

__device__ __forceinline__ int warp_exscan(int v, int lane) {
    int s = v;
    #pragma unroll
    for (int o = 1; o < 32; o <<= 1) {
        int u = __shfl_up_sync(0xffffffffu, s, o);
        if (lane >= o) s += u;
    }
    return s - v;
}

__global__ void __launch_bounds__(NTHR, 1) k_mega(
    const float* __restrict__ x, const int* __restrict__ ei,
    const float* __restrict__ fw1, const float* __restrict__ w1,
    const float* __restrict__ b1, const float* __restrict__ fw2,
    const float* __restrict__ w2, const float* __restrict__ b2,
    float* __restrict__ out, int N, int E, int F, int nw)
{
    __shared__ float wsT[512 * 16];        // W1^T [f][c]
    __shared__ float scratch[16 * 64];     // xs tile, aliased as sA in phase 2
    __shared__ int   sB[8][CAP];           // per-warp CSR list (persistent)
    __shared__ float sDinv[8];
    __shared__ int   sDeg[8];

    const int tid = threadIdx.x, bid = blockIdx.x;
    const int gtid = bid * NTHR + tid;
    const int gstride = gridDim.x * NTHR;
    const int wb = tid >> 5, lane = tid & 31;
    const int row = bid * 8 + wb;          // this warp's node (grid = N/8)

    // ---- phase 0: clear bitmasks ----
    for (int i = gtid; i < 2 * N * nw; i += gstride) g_bits[i] = 0u;
    gbar(0);

    // ---- phase 1: edges ----
    if (gtid < E) {
        int s = ei[gtid], t = ei[E + gtid];
        atomicOr(&g_bits[s * nw + (t >> 5)], 1u << (t & 31));
        atomicOr(&g_bits[(N + t) * nw + (s >> 5)], 1u << (s & 31));
    }
    gbar(1);

    // ---- phase 2a: compact lists, deg union, dinv (all blocks) ----
    {
        int* sA = (int*)scratch;           // [8][CAP]
        const unsigned* arow = &g_bits[row * nw];
        const unsigned* brow = &g_bits[(size_t)(N + row) * nw];
        int base = lane * 64;

        unsigned a0 = (2 * lane     < nw) ? arow[2 * lane]     : 0u;
        unsigned a1 = (2 * lane + 1 < nw) ? arow[2 * lane + 1] : 0u;
        int tot = __popc(a0) + __popc(a1);
        int off = warp_exscan(tot, lane);
        int degA = __shfl_sync(0xffffffffu, off + tot, 31);
        int pos = off;
        unsigned wt = a0;
        while (wt) { int bb = __ffs(wt) - 1; wt &= wt - 1; if (pos < CAP) sA[wb * CAP + pos] = base + bb; pos++; }
        wt = a1;
        while (wt) { int bb = __ffs(wt) - 1; wt &= wt - 1; if (pos < CAP) sA[wb * CAP + pos] = base + 32 + bb; pos++; }
        if (degA > CAP) degA = CAP;

        unsigned b0 = (2 * lane     < nw) ? brow[2 * lane]     : 0u;
        unsigned b1v = (2 * lane + 1 < nw) ? brow[2 * lane + 1] : 0u;
        int totB = __popc(b0) + __popc(b1v);
        int offB = warp_exscan(totB, lane);
        int degB = __shfl_sync(0xffffffffu, offB + totB, 31);
        int posB = offB;
        wt = b0;
        while (wt) { int bb = __ffs(wt) - 1; wt &= wt - 1; if (posB < CAP) sB[wb][posB] = base + bb; posB++; }
        wt = b1v;
        while (wt) { int bb = __ffs(wt) - 1; wt &= wt - 1; if (posB < CAP) sB[wb][posB] = base + 32 + bb; posB++; }
        if (lane == 0) sDeg[wb] = degB < CAP ? degB : CAP;
        __syncwarp();

        // deg union: {row} | Arow | OR_{j in Arow} Arow_j
        unsigned acc0 = (lane < nw)      ? arow[lane]      : 0u;
        unsigned acc1 = (lane + 32 < nw) ? arow[lane + 32] : 0u;
        int wi = row >> 5; unsigned ib = 1u << (row & 31);
        if (lane == wi)           acc0 |= ib;
        else if (lane + 32 == wi) acc1 |= ib;
        int k = 0;
        for (; k + 4 <= degA; k += 4) {
            const unsigned* r0 = &g_bits[sA[wb * CAP + k]     * nw];
            const unsigned* r1 = &g_bits[sA[wb * CAP + k + 1] * nw];
            const unsigned* r2 = &g_bits[sA[wb * CAP + k + 2] * nw];
            const unsigned* r3 = &g_bits[sA[wb * CAP + k + 3] * nw];
            if (lane < nw)      acc0 |= r0[lane]      | r1[lane]      | r2[lane]      | r3[lane];
            if (lane + 32 < nw) acc1 |= r0[lane + 32] | r1[lane + 32] | r2[lane + 32] | r3[lane + 32];
        }
        for (; k < degA; k++) {
            const unsigned* r = &g_bits[sA[wb * CAP + k] * nw];
            if (lane < nw)      acc0 |= r[lane];
            if (lane + 32 < nw) acc1 |= r[lane + 32];
        }
        int cnt = __popc(acc0) + __popc(acc1);
        cnt = __reduce_add_sync(0xffffffffu, cnt);
        if (lane == 0) { float dv = rsqrtf((float)cnt); sDinv[wb] = dv; g_dinv[row] = dv; }
    }
    __syncthreads();   // scratch: sA done -> xs

    // ---- phase 2b: GEMM h1 = x @ W1^T + b1 (first N/16 blocks) ----
    if (bid < (N >> 4)) {
        float (*xs)[64] = (float(*)[64])scratch;
        int row0 = bid * 16;
        for (int e = tid; e < 512 * 16; e += NTHR) {
            int c = e >> 9, f = e & 511;
            wsT[f * 16 + c] = w1[e];
        }
        __syncthreads();
        int r = tid >> 4, c = tid & 15;
        float acc = 0.f;
        for (int kc = 0; kc < F; kc += 64) {
            for (int e = tid; e < 16 * 64; e += NTHR) {
                int rr = e >> 6, k = e & 63;
                xs[rr][k] = x[(size_t)(row0 + rr) * F + kc + k];
            }
            __syncthreads();
            #pragma unroll 8
            for (int k = 0; k < 64; k++)
                acc = fmaf(xs[r][k], wsT[(kc + k) * 16 + c], acc);
            __syncthreads();
        }
        g_q[(row0 + r) * 16 + c] = acc + b1[c];
    }
    gbar(2);

    // ---- phase 3: spmm16  t1 = B (dinv .* h1) ----
    {
        int deg = sDeg[wb];
        float acc = 0.f;
        int k = 0;
        for (; k + 8 <= deg; k += 8) {
            int j0 = sB[wb][k],   j1 = sB[wb][k+1], j2 = sB[wb][k+2], j3 = sB[wb][k+3];
            int j4 = sB[wb][k+4], j5 = sB[wb][k+5], j6 = sB[wb][k+6], j7 = sB[wb][k+7];
            if (lane < 16) {
                float v0 = g_dinv[j0] * g_q[j0*16+lane], v1 = g_dinv[j1] * g_q[j1*16+lane];
                float v2 = g_dinv[j2] * g_q[j2*16+lane], v3 = g_dinv[j3] * g_q[j3*16+lane];
                float v4 = g_dinv[j4] * g_q[j4*16+lane], v5 = g_dinv[j5] * g_q[j5*16+lane];
                float v6 = g_dinv[j6] * g_q[j6*16+lane], v7 = g_dinv[j7] * g_q[j7*16+lane];
                acc = acc + v0 + v1 + v2 + v3 + v4 + v5 + v6 + v7;
            }
        }
        for (; k < deg; k++) {
            int j = sB[wb][k];
            if (lane < 16) acc += g_dinv[j] * g_q[j*16+lane];
        }
        if (lane < 16) g_t1[row * 16 + lane] = acc;
    }
    gbar(3);

    // ---- phase 4: l1post  t2=B t1; h=relu(d*(f0*d*q+f1*t1+f2*t2)); q2=d*(h@W2^T+b2)
    {
        int deg = sDeg[wb];
        float t2 = 0.f;
        int k = 0;
        for (; k + 8 <= deg; k += 8) {
            int j0 = sB[wb][k],   j1 = sB[wb][k+1], j2 = sB[wb][k+2], j3 = sB[wb][k+3];
            int j4 = sB[wb][k+4], j5 = sB[wb][k+5], j6 = sB[wb][k+6], j7 = sB[wb][k+7];
            if (lane < 16)
                t2 = t2 + g_t1[j0*16+lane] + g_t1[j1*16+lane] + g_t1[j2*16+lane]
                        + g_t1[j3*16+lane] + g_t1[j4*16+lane] + g_t1[j5*16+lane]
                        + g_t1[j6*16+lane] + g_t1[j7*16+lane];
        }
        for (; k < deg; k++) {
            int j = sB[wb][k];
            if (lane < 16) t2 += g_t1[j*16+lane];
        }
        float f0 = fw1[0], f1 = fw1[1], f2 = fw1[2];
        float d = sDinv[wb];
        float h1 = 0.f;
        if (lane < 16) {
            float r = f0 * d * g_q[row*16+lane] + f1 * g_t1[row*16+lane] + f2 * t2;
            h1 = fmaxf(d * r, 0.f);
        }
        float acc = b2[lane];
        #pragma unroll
        for (int k2 = 0; k2 < 16; k2++) {
            float hk = __shfl_sync(0xffffffffu, h1, k2);
            acc = fmaf(w2[lane * 16 + k2], hk, acc);
        }
        g_q2[row * 32 + lane] = d * acc;
    }
    gbar(4);

    // ---- phase 5: spmm32  t1 = B q2 ----
    {
        int deg = sDeg[wb];
        float acc = 0.f;
        int k = 0;
        for (; k + 8 <= deg; k += 8) {
            int j0 = sB[wb][k],   j1 = sB[wb][k+1], j2 = sB[wb][k+2], j3 = sB[wb][k+3];
            int j4 = sB[wb][k+4], j5 = sB[wb][k+5], j6 = sB[wb][k+6], j7 = sB[wb][k+7];
            acc = acc + g_q2[j0*32+lane] + g_q2[j1*32+lane] + g_q2[j2*32+lane]
                      + g_q2[j3*32+lane] + g_q2[j4*32+lane] + g_q2[j5*32+lane]
                      + g_q2[j6*32+lane] + g_q2[j7*32+lane];
        }
        for (; k < deg; k++) acc += g_q2[sB[wb][k]*32+lane];
        g_t1[row * 32 + lane] = acc;
    }
    gbar(5);

    // ---- phase 6: l2post  t2=B t1; z=d*(f0*q2+f1*t1+f2*t2); log_softmax ----
    {
        int deg = sDeg[wb];
        float t2 = 0.f;
        int k = 0;
        for (; k + 8 <= deg; k += 8) {
            int j0 = sB[wb][k],   j1 = sB[wb][k+1], j2 = sB[wb][k+2], j3 = sB[wb][k+3];
            int j4 = sB[wb][k+4], j5 = sB[wb][k+5], j6 = sB[wb][k+6], j7 = sB[wb][k+7];
            t2 = t2 + g_t1[j0*32+lane] + g_t1[j1*32+lane] + g_t1[j2*32+lane]
                    + g_t1[j3*32+lane] + g_t1[j4*32+lane] + g_t1[j5*32+lane]
                    + g_t1[j6*32+lane] + g_t1[j7*32+lane];
        }
        for (; k < deg; k++) t2 += g_t1[sB[wb][k]*32+lane];
        float f0 = fw2[0], f1 = fw2[1], f2 = fw2[2];
        float d = sDinv[wb];
        float z = d * (f0 * g_q2[row*32+lane] + f1 * g_t1[row*32+lane] + f2 * t2);
        float m = z;
        #pragma unroll
        for (int o = 16; o; o >>= 1) m = fmaxf(m, __shfl_xor_sync(0xffffffffu, m, o));
        float e = __expf(z - m);
        float s = e;
        #pragma unroll
        for (int o = 16; o; o >>= 1) s += __shfl_xor_sync(0xffffffffu, s, o);
        out[row * 32 + lane] = z - m - logf(s);
    }
}

extern "C" void kernel_launch(void* const* d_in, const int* in_sizes, int n_in,
                              void* d_out, int out_size) {
    const float* x   = (const float*)d_in[0];
    const int*   ei  = (const int*)  d_in[1];
    const float* fw1 = (const float*)d_in[2];
    const float* w1  = (const float*)d_in[3];
    const float* b1  = (const float*)d_in[4];
    const float* fw2 = (const float*)d_in[5];
    const float* w2  = (const float*)d_in[6];
    const float* b2  = (const float*)d_in[7];
    float* out = (float*)d_out;

    int H = in_sizes[4];            // 16
    int F = in_sizes[3] / H;        // 512
    int N = in_sizes[0] / F;        // 2048
    int E = in_sizes[1] / 2;        // 32768
    int nw = (N + 31) / 32;         // 64

    int grid = N / 8;               // 256 blocks, 8 rows each (co-resident)
    k_mega<<<grid, NTHR>>>(x, ei, fw1, w1, b1, fw2, w2, b2, out, N, E, F, nw);
}

// round 5
// speedup vs baseline: 3.1518x; 1.3354x over previous
#include <cuda_runtime.h>
#include <math.h>

// DoublePAN, single persistent kernel, round 5.
//  - GEMM (x@W1^T, no graph dependency) runs BEFORE the first grid barrier,
//    concurrent with the edge atomicOrs; warp-per-row, W1 in smem, LDS.128.
//  - Bitmask clear moved to kernel END (invariant: g_bits zero at entry —
//    statically zeroed on first call, re-zeroed before every exit).
//  - 5 grid barriers (monotonic tickets, replay-safe).
// Phases: [edges || GEMM] b0 [deg+lists] b1 [spmm16] b2 [l1post] b3
//         [spmm32] b4 [l2post; clear bits]

#define MAXN 2048
#define MAXNW (MAXN / 32)
#define CAP 128
#define NTHR 256

__device__ __align__(16) unsigned g_bits[2 * MAXN * MAXNW]; // A rows then B rows
__device__ unsigned g_barctr[8];              // monotonic, never reset
__device__ float    g_dinv[MAXN];
__device__ float    g_q [MAXN * 16];          // h1 (unscaled)
__device__ float    g_t1[MAXN * 32];
__device__ float    g_q2[MAXN * 32];

__device__ __forceinline__ void gbar(int idx) {
    __threadfence();
    __syncthreads();
    if (threadIdx.x == 0) {
        unsigned nb = gridDim.x;
        unsigned t = atomicAdd(&g_barctr[idx], 1u);
        unsigned target = t - (t % nb) + nb;
        while ((int)(*(volatile unsigned*)&g_barctr[idx] - target) < 0)
            __nanosleep(16);
        __threadfence();
    }
    __syncthreads();
}

__device__ __forceinline__ int warp_exscan(int v, int lane) {
    int s = v;
    #pragma unroll
    for (int o = 1; o < 32; o <<= 1) {
        int u = __shfl_up_sync(0xffffffffu, s, o);
        if (lane >= o) s += u;
    }
    return s - v;
}

__global__ void __launch_bounds__(NTHR) k_mega(
    const float* __restrict__ x, const int* __restrict__ ei,
    const float* __restrict__ fw1, const float* __restrict__ w1,
    const float* __restrict__ b1, const float* __restrict__ fw2,
    const float* __restrict__ w2, const float* __restrict__ b2,
    float* __restrict__ out, int N, int E, int F, int nw)
{
    __shared__ __align__(16) float sW[16 * 512]; // W1 [c][f]; aliased as sA later
    __shared__ int   sB[8][CAP];                 // per-warp CSR list (persistent)
    __shared__ float sDinv[8];
    __shared__ int   sDeg[8];

    const int tid = threadIdx.x, bid = blockIdx.x;
    const int gtid = bid * NTHR + tid;
    const int wb = tid >> 5, lane = tid & 31;
    const int row = bid * 8 + wb;          // this warp's node (grid = N/8)

    // ---- edges (bits are zero on entry — invariant) ----
    if (gtid < E) {
        int s = ei[gtid], t = ei[E + gtid];
        atomicOr(&g_bits[s * nw + (t >> 5)], 1u << (t & 31));
        atomicOr(&g_bits[(N + t) * nw + (s >> 5)], 1u << (s & 31));
    }

    // ---- GEMM h1 = x @ W1^T + b1 (no graph dependency; before bar 0) ----
    {
        for (int e = tid; e < 16 * 512; e += NTHR) sW[e] = w1[e]; // [c][f] verbatim
        __syncthreads();
        // warp per row; lane owns float4 k-chunks: k4 = lane + 32*i, i=0..3
        const float4* x4 = (const float4*)(x + (size_t)row * F);
        float4 xv[4];
        #pragma unroll
        for (int i = 0; i < 4; i++) xv[i] = x4[lane + 32 * i];
        const float4* sW4 = (const float4*)sW;
        float acc[16];
        #pragma unroll
        for (int c = 0; c < 16; c++) acc[c] = 0.f;
        #pragma unroll
        for (int c = 0; c < 16; c++) {
            #pragma unroll
            for (int i = 0; i < 4; i++) {
                float4 wv = sW4[c * 128 + lane + 32 * i];   // conflict-free LDS.128
                acc[c] = fmaf(xv[i].x, wv.x, acc[c]);
                acc[c] = fmaf(xv[i].y, wv.y, acc[c]);
                acc[c] = fmaf(xv[i].z, wv.z, acc[c]);
                acc[c] = fmaf(xv[i].w, wv.w, acc[c]);
            }
        }
        float outv = 0.f;
        #pragma unroll
        for (int c = 0; c < 16; c++) {
            float v = acc[c];
            #pragma unroll
            for (int o = 16; o; o >>= 1) v += __shfl_xor_sync(0xffffffffu, v, o);
            if (lane == c) outv = v;
        }
        if (lane < 16) g_q[row * 16 + lane] = outv + b1[lane];
    }
    gbar(0);

    // ---- deg + lists (sA aliases sW storage; safe: gbar has syncthreads) ----
    {
        int* sA = (int*)sW;                // [8][CAP]
        const unsigned* arow = &g_bits[row * nw];
        const unsigned* brow = &g_bits[(size_t)(N + row) * nw];
        int base = lane * 64;

        unsigned a0 = (2 * lane     < nw) ? arow[2 * lane]     : 0u;
        unsigned a1 = (2 * lane + 1 < nw) ? arow[2 * lane + 1] : 0u;
        int tot = __popc(a0) + __popc(a1);
        int off = warp_exscan(tot, lane);
        int degA = __shfl_sync(0xffffffffu, off + tot, 31);
        int pos = off;
        unsigned wt = a0;
        while (wt) { int bb = __ffs(wt) - 1; wt &= wt - 1; if (pos < CAP) sA[wb * CAP + pos] = base + bb; pos++; }
        wt = a1;
        while (wt) { int bb = __ffs(wt) - 1; wt &= wt - 1; if (pos < CAP) sA[wb * CAP + pos] = base + 32 + bb; pos++; }
        if (degA > CAP) degA = CAP;

        unsigned b0 = (2 * lane     < nw) ? brow[2 * lane]     : 0u;
        unsigned b1v = (2 * lane + 1 < nw) ? brow[2 * lane + 1] : 0u;
        int totB = __popc(b0) + __popc(b1v);
        int offB = warp_exscan(totB, lane);
        int degB = __shfl_sync(0xffffffffu, offB + totB, 31);
        int posB = offB;
        wt = b0;
        while (wt) { int bb = __ffs(wt) - 1; wt &= wt - 1; if (posB < CAP) sB[wb][posB] = base + bb; posB++; }
        wt = b1v;
        while (wt) { int bb = __ffs(wt) - 1; wt &= wt - 1; if (posB < CAP) sB[wb][posB] = base + 32 + bb; posB++; }
        if (lane == 0) sDeg[wb] = degB < CAP ? degB : CAP;
        __syncwarp();

        unsigned acc0 = (lane < nw)      ? arow[lane]      : 0u;
        unsigned acc1 = (lane + 32 < nw) ? arow[lane + 32] : 0u;
        int wi = row >> 5; unsigned ib = 1u << (row & 31);
        if (lane == wi)           acc0 |= ib;
        else if (lane + 32 == wi) acc1 |= ib;
        int k = 0;
        for (; k + 4 <= degA; k += 4) {
            const unsigned* r0 = &g_bits[sA[wb * CAP + k]     * nw];
            const unsigned* r1 = &g_bits[sA[wb * CAP + k + 1] * nw];
            const unsigned* r2 = &g_bits[sA[wb * CAP + k + 2] * nw];
            const unsigned* r3 = &g_bits[sA[wb * CAP + k + 3] * nw];
            if (lane < nw)      acc0 |= r0[lane]      | r1[lane]      | r2[lane]      | r3[lane];
            if (lane + 32 < nw) acc1 |= r0[lane + 32] | r1[lane + 32] | r2[lane + 32] | r3[lane + 32];
        }
        for (; k < degA; k++) {
            const unsigned* r = &g_bits[sA[wb * CAP + k] * nw];
            if (lane < nw)      acc0 |= r[lane];
            if (lane + 32 < nw) acc1 |= r[lane + 32];
        }
        int cnt = __popc(acc0) + __popc(acc1);
        cnt = __reduce_add_sync(0xffffffffu, cnt);
        if (lane == 0) { float dv = rsqrtf((float)cnt); sDinv[wb] = dv; g_dinv[row] = dv; }
    }
    gbar(1);

    // ---- spmm16: t1 = B (dinv .* h1) ----
    {
        int deg = sDeg[wb];
        float acc = 0.f;
        int k = 0;
        for (; k + 8 <= deg; k += 8) {
            int j0 = sB[wb][k],   j1 = sB[wb][k+1], j2 = sB[wb][k+2], j3 = sB[wb][k+3];
            int j4 = sB[wb][k+4], j5 = sB[wb][k+5], j6 = sB[wb][k+6], j7 = sB[wb][k+7];
            if (lane < 16) {
                float v0 = g_dinv[j0] * g_q[j0*16+lane], v1 = g_dinv[j1] * g_q[j1*16+lane];
                float v2 = g_dinv[j2] * g_q[j2*16+lane], v3 = g_dinv[j3] * g_q[j3*16+lane];
                float v4 = g_dinv[j4] * g_q[j4*16+lane], v5 = g_dinv[j5] * g_q[j5*16+lane];
                float v6 = g_dinv[j6] * g_q[j6*16+lane], v7 = g_dinv[j7] * g_q[j7*16+lane];
                acc = acc + v0 + v1 + v2 + v3 + v4 + v5 + v6 + v7;
            }
        }
        for (; k < deg; k++) {
            int j = sB[wb][k];
            if (lane < 16) acc += g_dinv[j] * g_q[j*16+lane];
        }
        if (lane < 16) g_t1[row * 16 + lane] = acc;
    }
    gbar(2);

    // ---- l1post: t2=B t1; h=relu(d*(f0*d*q+f1*t1+f2*t2)); q2=d*(h@W2^T+b2)
    {
        int deg = sDeg[wb];
        float t2 = 0.f;
        int k = 0;
        for (; k + 8 <= deg; k += 8) {
            int j0 = sB[wb][k],   j1 = sB[wb][k+1], j2 = sB[wb][k+2], j3 = sB[wb][k+3];
            int j4 = sB[wb][k+4], j5 = sB[wb][k+5], j6 = sB[wb][k+6], j7 = sB[wb][k+7];
            if (lane < 16)
                t2 = t2 + g_t1[j0*16+lane] + g_t1[j1*16+lane] + g_t1[j2*16+lane]
                        + g_t1[j3*16+lane] + g_t1[j4*16+lane] + g_t1[j5*16+lane]
                        + g_t1[j6*16+lane] + g_t1[j7*16+lane];
        }
        for (; k < deg; k++) {
            int j = sB[wb][k];
            if (lane < 16) t2 += g_t1[j*16+lane];
        }
        float f0 = fw1[0], f1 = fw1[1], f2 = fw1[2];
        float d = sDinv[wb];
        float h1 = 0.f;
        if (lane < 16) {
            float r = f0 * d * g_q[row*16+lane] + f1 * g_t1[row*16+lane] + f2 * t2;
            h1 = fmaxf(d * r, 0.f);
        }
        float acc = b2[lane];
        #pragma unroll
        for (int k2 = 0; k2 < 16; k2++) {
            float hk = __shfl_sync(0xffffffffu, h1, k2);
            acc = fmaf(w2[lane * 16 + k2], hk, acc);
        }
        g_q2[row * 32 + lane] = d * acc;
    }
    gbar(3);

    // ---- spmm32: t1 = B q2 ----
    {
        int deg = sDeg[wb];
        float acc = 0.f;
        int k = 0;
        for (; k + 8 <= deg; k += 8) {
            int j0 = sB[wb][k],   j1 = sB[wb][k+1], j2 = sB[wb][k+2], j3 = sB[wb][k+3];
            int j4 = sB[wb][k+4], j5 = sB[wb][k+5], j6 = sB[wb][k+6], j7 = sB[wb][k+7];
            acc = acc + g_q2[j0*32+lane] + g_q2[j1*32+lane] + g_q2[j2*32+lane]
                      + g_q2[j3*32+lane] + g_q2[j4*32+lane] + g_q2[j5*32+lane]
                      + g_q2[j6*32+lane] + g_q2[j7*32+lane];
        }
        for (; k < deg; k++) acc += g_q2[sB[wb][k]*32+lane];
        g_t1[row * 32 + lane] = acc;
    }
    gbar(4);

    // ---- l2post: t2=B t1; z=d*(f0*q2+f1*t1+f2*t2); log_softmax -> out ----
    {
        int deg = sDeg[wb];
        float t2 = 0.f;
        int k = 0;
        for (; k + 8 <= deg; k += 8) {
            int j0 = sB[wb][k],   j1 = sB[wb][k+1], j2 = sB[wb][k+2], j3 = sB[wb][k+3];
            int j4 = sB[wb][k+4], j5 = sB[wb][k+5], j6 = sB[wb][k+6], j7 = sB[wb][k+7];
            t2 = t2 + g_t1[j0*32+lane] + g_t1[j1*32+lane] + g_t1[j2*32+lane]
                    + g_t1[j3*32+lane] + g_t1[j4*32+lane] + g_t1[j5*32+lane]
                    + g_t1[j6*32+lane] + g_t1[j7*32+lane];
        }
        for (; k < deg; k++) t2 += g_t1[sB[wb][k]*32+lane];
        float f0 = fw2[0], f1 = fw2[1], f2 = fw2[2];
        float d = sDinv[wb];
        float z = d * (f0 * g_q2[row*32+lane] + f1 * g_t1[row*32+lane] + f2 * t2);
        float m = z;
        #pragma unroll
        for (int o = 16; o; o >>= 1) m = fmaxf(m, __shfl_xor_sync(0xffffffffu, m, o));
        float e = __expf(z - m);
        float s = e;
        #pragma unroll
        for (int o = 16; o; o >>= 1) s += __shfl_xor_sync(0xffffffffu, s, o);
        out[row * 32 + lane] = z - m - logf(s);
    }

    // ---- restore invariant: zero g_bits for the next replay ----
    // (g_bits last read in deg phase, which all blocks passed at bar(1))
    ((uint4*)g_bits)[gtid] = make_uint4(0u, 0u, 0u, 0u);
}

extern "C" void kernel_launch(void* const* d_in, const int* in_sizes, int n_in,
                              void* d_out, int out_size) {
    const float* x   = (const float*)d_in[0];
    const int*   ei  = (const int*)  d_in[1];
    const float* fw1 = (const float*)d_in[2];
    const float* w1  = (const float*)d_in[3];
    const float* b1  = (const float*)d_in[4];
    const float* fw2 = (const float*)d_in[5];
    const float* w2  = (const float*)d_in[6];
    const float* b2  = (const float*)d_in[7];
    float* out = (float*)d_out;

    int H = in_sizes[4];            // 16
    int F = in_sizes[3] / H;        // 512
    int N = in_sizes[0] / F;        // 2048
    int E = in_sizes[1] / 2;        // 32768
    int nw = (N + 31) / 32;         // 64

    int grid = N / 8;               // 256 blocks; 2*N*nw/4 = grid*NTHR uint4
    k_mega<<<grid, NTHR>>>(x, ei, fw1, w1, b1, fw2, w2, b2, out, N, E, F, nw);
}